// round 1
// baseline (speedup 1.0000x reference)
#include <cuda_runtime.h>
#include <math.h>

// Problem dims (fixed by setup_inputs)
#define Bsz 16
#define Tn  1024
#define Dn  1024
#define Hn  4096
#define BT  (Bsz*Tn)              // 16384
#define BTD (Bsz*Tn*Dn)           // 16777216
#define BTH (Bsz*Tn*Hn)           // 67108864
#define CONVK 4

// ---------------- scratch (device globals; no allocations allowed) ----------
__device__ float g_norm[BTD];   // rmsnorm1 output
__device__ float g_b1[BTD];     // normed @ W1^T
__device__ float g_conv[BTD];   // depthwise conv output
__device__ float g_r[BTD];      // sigmoid(conv@Wa^T+ba)
__device__ float g_i[BTD];      // sigmoid(conv@Wx^T+bx) -> then holds a
__device__ float g_u[BTD];      // u
__device__ float g_scan[BTD];   // scan output (b1_out)
__device__ float g_b2[BTD];     // gelu(normed@W2^T) -> then b1_out*b2
__device__ float g_x1[BTD];     // x_seq + recurrent_out
__device__ float g_n2[BTD];     // rmsnorm2 output
__device__ float g_gl[BTH];     // gelu(n2@Wg^T)
__device__ float g_act[BTH];    // (n2@Wu^T) * g_gl

// ---------------- helpers ---------------------------------------------------
__device__ __forceinline__ float gelu_f(float x) {
    return 0.5f * x * (1.0f + erff(x * 0.70710678118654752440f));
}

// ---------------- RMSNorm: one block per row of D=1024 ----------------------
__global__ void rmsnorm_k(const float* __restrict__ x, const float* __restrict__ w,
                          float* __restrict__ out) {
    const long row = blockIdx.x;
    const float* xr = x + row * (long)Dn;
    const int t4 = threadIdx.x * 4;
    float4 v = *(const float4*)(xr + t4);
    float ss = v.x*v.x + v.y*v.y + v.z*v.z + v.w*v.w;
    #pragma unroll
    for (int o = 16; o > 0; o >>= 1) ss += __shfl_xor_sync(0xffffffffu, ss, o);
    __shared__ float warps[8];
    if ((threadIdx.x & 31) == 0) warps[threadIdx.x >> 5] = ss;
    __syncthreads();
    float tot = 0.f;
    #pragma unroll
    for (int i = 0; i < 8; i++) tot += warps[i];
    const float inv = rsqrtf(tot * (1.0f / Dn) + 1.1920929e-07f);
    float4 wv = *(const float4*)(w + t4);
    float4 o4;
    o4.x = v.x * inv * wv.x;
    o4.y = v.y * inv * wv.y;
    o4.z = v.z * inv * wv.z;
    o4.w = v.w * inv * wv.w;
    *(float4*)(out + row * (long)Dn + t4) = o4;
}

// ---------------- SGEMM NT: C[M,N] = A[M,K] @ B[N,K]^T, fused epilogues -----
// EPI: 0=none 1=sigmoid(v+bias[col]) 2=gelu(v) 3=v+aux[idx] 4=v*aux[idx]
template<int EPI>
__global__ __launch_bounds__(256, 2)
void gemm_nt(const float* __restrict__ A, const float* __restrict__ Bm,
             float* __restrict__ C, int M, int N, int K,
             const float* __restrict__ bias, const float* __restrict__ aux) {
    __shared__ float As[16][128];
    __shared__ float Bs[16][128];
    const int tid = threadIdx.x;
    const int tx = tid & 15;
    const int ty = tid >> 4;
    const long bM = (long)blockIdx.y * 128;
    const long bN = (long)blockIdx.x * 128;
    const float* Ap = A + bM * K;
    const float* Bp = Bm + bN * K;
    const int lr = tid >> 2;          // 0..63
    const int lc = (tid & 3) << 2;    // 0,4,8,12

    float acc[8][8];
    #pragma unroll
    for (int i = 0; i < 8; i++)
        #pragma unroll
        for (int j = 0; j < 8; j++) acc[i][j] = 0.f;

    for (int k0 = 0; k0 < K; k0 += 16) {
        float4 a0 = *(const float4*)(Ap + (long)lr * K + k0 + lc);
        float4 a1 = *(const float4*)(Ap + (long)(lr + 64) * K + k0 + lc);
        float4 b0 = *(const float4*)(Bp + (long)lr * K + k0 + lc);
        float4 b1 = *(const float4*)(Bp + (long)(lr + 64) * K + k0 + lc);
        __syncthreads();
        As[lc+0][lr] = a0.x; As[lc+1][lr] = a0.y; As[lc+2][lr] = a0.z; As[lc+3][lr] = a0.w;
        As[lc+0][lr+64] = a1.x; As[lc+1][lr+64] = a1.y; As[lc+2][lr+64] = a1.z; As[lc+3][lr+64] = a1.w;
        Bs[lc+0][lr] = b0.x; Bs[lc+1][lr] = b0.y; Bs[lc+2][lr] = b0.z; Bs[lc+3][lr] = b0.w;
        Bs[lc+0][lr+64] = b1.x; Bs[lc+1][lr+64] = b1.y; Bs[lc+2][lr+64] = b1.z; Bs[lc+3][lr+64] = b1.w;
        __syncthreads();
        #pragma unroll
        for (int k = 0; k < 16; k++) {
            float ra[8], rb[8];
            *(float4*)(ra)     = *(const float4*)&As[k][ty * 8];
            *(float4*)(ra + 4) = *(const float4*)&As[k][ty * 8 + 4];
            *(float4*)(rb)     = *(const float4*)&Bs[k][tx * 8];
            *(float4*)(rb + 4) = *(const float4*)&Bs[k][tx * 8 + 4];
            #pragma unroll
            for (int i = 0; i < 8; i++)
                #pragma unroll
                for (int j = 0; j < 8; j++)
                    acc[i][j] = fmaf(ra[i], rb[j], acc[i][j]);
        }
    }

    #pragma unroll
    for (int i = 0; i < 8; i++) {
        const long row = bM + ty * 8 + i;
        const long colBase = bN + tx * 8;
        float* Cp = C + row * (long)N + colBase;
        const float* Xp = (EPI == 3 || EPI == 4) ? (aux + row * (long)N + colBase) : nullptr;
        float out[8];
        #pragma unroll
        for (int j = 0; j < 8; j++) {
            float v = acc[i][j];
            if (EPI == 1)      v = 1.f / (1.f + expf(-(v + bias[colBase + j])));
            else if (EPI == 2) v = gelu_f(v);
            else if (EPI == 3) v = v + Xp[j];
            else if (EPI == 4) v = v * Xp[j];
            out[j] = v;
        }
        *(float4*)(Cp)     = *(const float4*)(out);
        *(float4*)(Cp + 4) = *(const float4*)(out + 4);
    }
}

// ---------------- depthwise causal conv (K=4) -------------------------------
__global__ void conv_kernel(const float* __restrict__ b1, const float* __restrict__ cbuf,
                            const float* __restrict__ cw, const float* __restrict__ cb,
                            float* __restrict__ out) {
    const long idx = (long)blockIdx.x * 256 + threadIdx.x;
    if (idx >= BTD) return;
    const int d = (int)(idx % Dn);
    const long td = idx / Dn;
    const int t = (int)(td % Tn);
    const int b = (int)(td / Tn);
    float acc = cb[d];
    #pragma unroll
    for (int k = 0; k < CONVK; k++) {
        const int tt = t + k - (CONVK - 1);
        float v = (tt >= 0) ? b1[((long)b * Tn + tt) * Dn + d]
                            : cbuf[((long)b * (CONVK - 1) + (t + k)) * Dn + d];
        acc = fmaf(v, cw[d * CONVK + k], acc);
    }
    out[idx] = acc;
}

// ---------------- gate: a = exp(8 r logsig(l)); u = sqrt((1-a)(1+a)) i conv -
__global__ void gate_k(const float* __restrict__ r, float* __restrict__ ia,
                       const float* __restrict__ conv, const float* __restrict__ ll,
                       float* __restrict__ u) {
    const long idx = (long)blockIdx.x * 256 + threadIdx.x;
    if (idx >= BTD) return;
    const int d = (int)(idx % Dn);
    const float lam = ll[d];
    const float ls = -log1pf(expf(-lam));          // log_sigmoid
    const float a = expf(8.0f * r[idx] * ls);
    const float gate = sqrtf(fmaxf((1.f - a) * (1.f + a), 1e-6f));
    const float uu = gate * ia[idx] * conv[idx];
    ia[idx] = a;
    u[idx] = uu;
}

// ---------------- linear scan over T (one thread per (b,d) chain) -----------
__global__ void scan_k(const float* __restrict__ a, const float* __restrict__ u,
                       const float* __restrict__ h0, float* __restrict__ out,
                       float* __restrict__ newh) {
    const int idx = blockIdx.x * 256 + threadIdx.x;   // 0..B*D-1
    const int b = idx / Dn, d = idx % Dn;
    const long base = (long)b * Tn * Dn + d;
    float h = h0[idx];
    #pragma unroll 4
    for (int t = 0; t < Tn; t++) {
        const long o = base + (long)t * Dn;
        h = fmaf(a[o], h, u[o]);
        out[o] = h;
    }
    newh[idx] = h;
}

// ---------------- elementwise multiply (b2 *= scan) -------------------------
__global__ void mul_k(float* __restrict__ x, const float* __restrict__ y) {
    const long idx = (long)blockIdx.x * 256 + threadIdx.x;
    if (idx >= BTD) return;
    x[idx] = x[idx] * y[idx];
}

// ---------------- copy new_conv_buf = b1[:, T-3:T, :] -----------------------
__global__ void cbuf_k(const float* __restrict__ b1, float* __restrict__ out) {
    const int idx = blockIdx.x * 256 + threadIdx.x;   // 0..B*3*D-1
    if (idx >= Bsz * (CONVK - 1) * Dn) return;
    const int d = idx % Dn;
    const int j = (idx / Dn) % (CONVK - 1);
    const int b = idx / (Dn * (CONVK - 1));
    out[idx] = b1[((long)b * Tn + (Tn - (CONVK - 1) + j)) * Dn + d];
}

// ---------------- launcher ---------------------------------------------------
extern "C" void kernel_launch(void* const* d_in, const int* in_sizes, int n_in,
                              void* d_out, int out_size) {
    const float* x_seq   = (const float*)d_in[0];
    const float* h0      = (const float*)d_in[1];
    const float* convbuf = (const float*)d_in[2];
    const float* norm1_w = (const float*)d_in[3];
    const float* W1      = (const float*)d_in[4];
    const float* conv_w  = (const float*)d_in[5];
    const float* conv_b  = (const float*)d_in[6];
    const float* Wa      = (const float*)d_in[7];
    const float* ba      = (const float*)d_in[8];
    const float* Wx      = (const float*)d_in[9];
    const float* bx      = (const float*)d_in[10];
    const float* log_lam = (const float*)d_in[11];
    const float* W2      = (const float*)d_in[12];
    const float* Wout    = (const float*)d_in[13];
    const float* norm2_w = (const float*)d_in[14];
    const float* Wg      = (const float*)d_in[15];
    const float* Wu      = (const float*)d_in[16];
    const float* Wo      = (const float*)d_in[17];

    float* out_x2 = (float*)d_out;
    float* out_h  = out_x2 + (long)BTD;
    float* out_cb = out_h + (long)Bsz * Dn;

    float *p_norm, *p_b1, *p_conv, *p_r, *p_i, *p_u, *p_scan, *p_b2, *p_x1, *p_n2, *p_gl, *p_act;
    cudaGetSymbolAddress((void**)&p_norm, g_norm);
    cudaGetSymbolAddress((void**)&p_b1,   g_b1);
    cudaGetSymbolAddress((void**)&p_conv, g_conv);
    cudaGetSymbolAddress((void**)&p_r,    g_r);
    cudaGetSymbolAddress((void**)&p_i,    g_i);
    cudaGetSymbolAddress((void**)&p_u,    g_u);
    cudaGetSymbolAddress((void**)&p_scan, g_scan);
    cudaGetSymbolAddress((void**)&p_b2,   g_b2);
    cudaGetSymbolAddress((void**)&p_x1,   g_x1);
    cudaGetSymbolAddress((void**)&p_n2,   g_n2);
    cudaGetSymbolAddress((void**)&p_gl,   g_gl);
    cudaGetSymbolAddress((void**)&p_act,  g_act);

    const dim3 gD(Dn / 128, BT / 128);   // (8, 128)
    const dim3 gH(Hn / 128, BT / 128);   // (32, 128)
    const int EW = (BTD + 255) / 256;

    // 1. rmsnorm1
    rmsnorm_k<<<BT, 256>>>(x_seq, norm1_w, p_norm);
    // 2. b1 = normed @ W1^T
    gemm_nt<0><<<gD, 256>>>(p_norm, W1, p_b1, BT, Dn, Dn, nullptr, nullptr);
    // 3. conv + new_conv_buf
    conv_kernel<<<EW, 256>>>(p_b1, convbuf, conv_w, conv_b, p_conv);
    cbuf_k<<<(Bsz * (CONVK - 1) * Dn + 255) / 256, 256>>>(p_b1, out_cb);
    // 4/5. r, i
    gemm_nt<1><<<gD, 256>>>(p_conv, Wa, p_r, BT, Dn, Dn, ba, nullptr);
    gemm_nt<1><<<gD, 256>>>(p_conv, Wx, p_i, BT, Dn, Dn, bx, nullptr);
    // 6. a, u
    gate_k<<<EW, 256>>>(p_r, p_i, p_conv, log_lam, p_u);
    // 7. scan
    scan_k<<<(Bsz * Dn) / 256, 256>>>(p_i, p_u, h0, p_scan, out_h);
    // 8. b2 = gelu(normed @ W2^T)
    gemm_nt<2><<<gD, 256>>>(p_norm, W2, p_b2, BT, Dn, Dn, nullptr, nullptr);
    // 9. b2 *= scan
    mul_k<<<EW, 256>>>(p_b2, p_scan);
    // 10. x1 = x_seq + b2 @ Wout^T
    gemm_nt<3><<<gD, 256>>>(p_b2, Wout, p_x1, BT, Dn, Dn, nullptr, x_seq);
    // 11. n2 = rmsnorm(x1)
    rmsnorm_k<<<BT, 256>>>(p_x1, norm2_w, p_n2);
    // 12. gl = gelu(n2 @ Wg^T)
    gemm_nt<2><<<gH, 256>>>(p_n2, Wg, p_gl, BT, Hn, Dn, nullptr, nullptr);
    // 13. act = (n2 @ Wu^T) * gl
    gemm_nt<4><<<gH, 256>>>(p_n2, Wu, p_act, BT, Hn, Dn, nullptr, p_gl);
    // 14. x2 = x1 + act @ Wo^T
    gemm_nt<3><<<gD, 256>>>(p_act, Wo, out_x2, BT, Dn, Hn, nullptr, p_x1);
}

// round 3
// speedup vs baseline: 2.0110x; 2.0110x over previous
#include <cuda_runtime.h>
#include <cuda_bf16.h>
#include <math.h>
#include <stdint.h>

// ---------------- problem dims ----------------
#define Bsz 16
#define Tn  1024
#define Dn  1024
#define Hn  4096
#define BT  (Bsz*Tn)              // 16384
#define BTD (Bsz*Tn*Dn)           // 16777216
#define BTH (Bsz*Tn*Hn)           // 67108864
#define CONVK 4

// ---------------- GEMM tile config ----------------
#define STAGES 4
#define TILE_BYTES  10240         // 128 rows x 80B (stride 40 bf16)
#define STAGE_BYTES 40960         // Ahi, Alo, Bhi, Blo
#define SMEM_BYTES  (STAGES*STAGE_BYTES)   // 163840

// ---------------- scratch (device globals) ----------------
__device__ __align__(128) float g_b1[BTD];
__device__ __align__(128) float g_conv[BTD];
__device__ __align__(128) float g_r[BTD];
__device__ __align__(128) float g_i[BTD];     // sigmoid i -> then a
__device__ __align__(128) float g_u[BTD];
__device__ __align__(128) float g_scan[BTD];
__device__ __align__(128) float g_b2[BTD];
__device__ __align__(128) float g_x1[BTD];
__device__ __align__(128) float g_gl[BTH];

__device__ __align__(128) __nv_bfloat16 g_norm_h[BTD], g_norm_l[BTD];
__device__ __align__(128) __nv_bfloat16 g_conv_h[BTD], g_conv_l[BTD];
__device__ __align__(128) __nv_bfloat16 g_prod_h[BTD], g_prod_l[BTD];
__device__ __align__(128) __nv_bfloat16 g_n2_h[BTD],   g_n2_l[BTD];
__device__ __align__(128) __nv_bfloat16 g_act_h[BTH],  g_act_l[BTH];

__device__ __align__(128) __nv_bfloat16 g_w1_h[Dn*Dn],  g_w1_l[Dn*Dn];
__device__ __align__(128) __nv_bfloat16 g_wa_h[Dn*Dn],  g_wa_l[Dn*Dn];
__device__ __align__(128) __nv_bfloat16 g_wx_h[Dn*Dn],  g_wx_l[Dn*Dn];
__device__ __align__(128) __nv_bfloat16 g_w2_h[Dn*Dn],  g_w2_l[Dn*Dn];
__device__ __align__(128) __nv_bfloat16 g_wo_h[Dn*Dn],  g_wo_l[Dn*Dn];     // Wout
__device__ __align__(128) __nv_bfloat16 g_wg_h[Hn*Dn],  g_wg_l[Hn*Dn];
__device__ __align__(128) __nv_bfloat16 g_wu_h[Hn*Dn],  g_wu_l[Hn*Dn];
__device__ __align__(128) __nv_bfloat16 g_wout2_h[(long)Dn*Hn], g_wout2_l[(long)Dn*Hn]; // Wo

// ---------------- helpers ----------------
__device__ __forceinline__ uint32_t smem_u32(const void* p) {
    uint32_t a;
    asm("{ .reg .u64 t; cvta.to.shared.u64 t, %1; cvt.u32.u64 %0, t; }"
        : "=r"(a) : "l"(p));
    return a;
}
__device__ __forceinline__ float gelu_f(float x) {
    return 0.5f * x * (1.0f + erff(x * 0.70710678118654752440f));
}
__device__ __forceinline__ float sigm_f(float x) {
    return 1.0f / (1.0f + expf(-x));
}
__device__ __forceinline__ void split2(float v, __nv_bfloat16& h, __nv_bfloat16& l) {
    h = __float2bfloat16(v);
    l = __float2bfloat16(v - __bfloat162float(h));
}
__device__ __forceinline__ uint32_t packbf(__nv_bfloat16 a, __nv_bfloat16 b) {
    __nv_bfloat162 t = __halves2bfloat162(a, b);
    return *reinterpret_cast<uint32_t*>(&t);
}
__device__ __forceinline__ void ldsm4(uint32_t addr, uint32_t r[4]) {
    asm volatile("ldmatrix.sync.aligned.m8n8.x4.shared.b16 {%0,%1,%2,%3}, [%4];"
                 : "=r"(r[0]), "=r"(r[1]), "=r"(r[2]), "=r"(r[3]) : "r"(addr));
}
__device__ __forceinline__ void mma16816(float c[4], const uint32_t a[4], const uint32_t b[2]) {
    asm volatile("mma.sync.aligned.m16n8k16.row.col.f32.bf16.bf16.f32 "
                 "{%0,%1,%2,%3}, {%4,%5,%6,%7}, {%8,%9}, {%0,%1,%2,%3};"
                 : "+f"(c[0]), "+f"(c[1]), "+f"(c[2]), "+f"(c[3])
                 : "r"(a[0]), "r"(a[1]), "r"(a[2]), "r"(a[3]), "r"(b[0]), "r"(b[1]));
}
__device__ __forceinline__ void cp16(uint32_t dst, const void* src) {
    asm volatile("cp.async.cg.shared.global [%0], [%1], 16;" :: "r"(dst), "l"(src));
}
#define CP_COMMIT() asm volatile("cp.async.commit_group;" ::: "memory")
#define CP_WAIT2()  asm volatile("cp.async.wait_group 2;" ::: "memory")

// ================= GEMM: C[M,N] = A[M,K] @ B[N,K]^T (bf16 hi/lo x3) =========
// EPI: 0=none 1=sigmoid(v+bias[col]) 2=gelu 3=v+aux 4=v*aux
// HILO: 1 -> write bf16 hi/lo split to Chi/Clo instead of float C
template<int EPI, int HILO>
__global__ void __launch_bounds__(256, 1)
gemm_mma(const __nv_bfloat16* __restrict__ Ah, const __nv_bfloat16* __restrict__ Al,
         const __nv_bfloat16* __restrict__ Bh, const __nv_bfloat16* __restrict__ Bl,
         float* __restrict__ C, __nv_bfloat16* __restrict__ Chi,
         __nv_bfloat16* __restrict__ Clo,
         const float* __restrict__ aux, const float* __restrict__ bias,
         int N, int K)
{
    extern __shared__ __align__(128) char smem[];
    const uint32_t sb = smem_u32(smem);
    const int tid = threadIdx.x;
    const int lane = tid & 31, wid = tid >> 5;
    const int wm = wid & 1;            // 2 warps along M (64 rows each)
    const int wn = wid >> 1;           // 4 warps along N (32 cols each)
    const long rowA = (long)blockIdx.y * 128;
    const long rowB = (long)blockIdx.x * 128;
    const int nk = K >> 5;             // BK = 32

    float acc[4][4][4];
    #pragma unroll
    for (int i = 0; i < 4; i++)
        #pragma unroll
        for (int n = 0; n < 4; n++)
            #pragma unroll
            for (int q = 0; q < 4; q++) acc[i][n][q] = 0.f;

    auto load_tile = [&](uint32_t dst, const __nv_bfloat16* src, long row0, int k0) {
        #pragma unroll
        for (int t = 0; t < 2; t++) {
            const int idx = tid + t * 256;
            const int r = idx >> 2, c = idx & 3;
            cp16(dst + r * 80 + c * 16, src + (row0 + r) * (long)K + k0 + c * 8);
        }
    };
    auto load_stage = [&](int s, int kt) {
        const uint32_t base = sb + s * STAGE_BYTES;
        const int k0 = kt << 5;
        load_tile(base,         Ah, rowA, k0);
        load_tile(base + 10240, Al, rowA, k0);
        load_tile(base + 20480, Bh, rowB, k0);
        load_tile(base + 30720, Bl, rowB, k0);
    };

    load_stage(0, 0); CP_COMMIT();
    load_stage(1, 1); CP_COMMIT();
    load_stage(2, 2); CP_COMMIT();

    for (int kt = 0; kt < nk; kt++) {
        CP_WAIT2();
        __syncthreads();
        if (kt + 3 < nk) load_stage((kt + 3) & 3, kt + 3);
        CP_COMMIT();

        const uint32_t base = sb + (kt & 3) * STAGE_BYTES;
        #pragma unroll
        for (int kk = 0; kk < 2; kk++) {
            const uint32_t koff = (kk * 16 + (lane >> 4) * 8) * 2;   // byte offset in row
            uint32_t ah[4][4], al[4][4];
            #pragma unroll
            for (int i = 0; i < 4; i++) {
                const uint32_t off = (uint32_t)(wm * 64 + i * 16 + (lane & 15)) * 80 + koff;
                ldsm4(base + off, ah[i]);
                ldsm4(base + 10240 + off, al[i]);
            }
            uint32_t bh[4][2], bl[4][2];
            #pragma unroll
            for (int j = 0; j < 2; j++) {
                const uint32_t off = (uint32_t)(wn * 32 + j * 16 + (lane & 15)) * 80 + koff;
                uint32_t t[4], u[4];
                ldsm4(base + 20480 + off, t);
                ldsm4(base + 30720 + off, u);
                bh[2*j][0] = t[0]; bh[2*j][1] = t[2];
                bh[2*j+1][0] = t[1]; bh[2*j+1][1] = t[3];
                bl[2*j][0] = u[0]; bl[2*j][1] = u[2];
                bl[2*j+1][0] = u[1]; bl[2*j+1][1] = u[3];
            }
            #pragma unroll
            for (int i = 0; i < 4; i++)
                #pragma unroll
                for (int n = 0; n < 4; n++) {
                    mma16816(acc[i][n], ah[i], bh[n]);
                    mma16816(acc[i][n], ah[i], bl[n]);
                    mma16816(acc[i][n], al[i], bh[n]);
                }
        }
    }

    // ---- epilogue ----
    const long r0 = rowA + wm * 64 + (lane >> 2);
    const long c0 = rowB + wn * 32 + (lane & 3) * 2;
    #pragma unroll
    for (int i = 0; i < 4; i++) {
        #pragma unroll
        for (int n = 0; n < 4; n++) {
            #pragma unroll
            for (int h = 0; h < 2; h++) {
                const long row = r0 + i * 16 + h * 8;
                const long col = c0 + n * 8;
                float v0 = acc[i][n][2*h + 0];
                float v1 = acc[i][n][2*h + 1];
                if (EPI == 1) {
                    v0 = sigm_f(v0 + bias[col]);
                    v1 = sigm_f(v1 + bias[col + 1]);
                } else if (EPI == 2) {
                    v0 = gelu_f(v0); v1 = gelu_f(v1);
                } else if (EPI == 3) {
                    const float2 a2 = *(const float2*)(aux + row * (long)N + col);
                    v0 += a2.x; v1 += a2.y;
                } else if (EPI == 4) {
                    const float2 a2 = *(const float2*)(aux + row * (long)N + col);
                    v0 *= a2.x; v1 *= a2.y;
                }
                if (HILO) {
                    __nv_bfloat16 h0, l0, h1, l1;
                    split2(v0, h0, l0); split2(v1, h1, l1);
                    *(uint32_t*)(Chi + row * (long)N + col) = packbf(h0, h1);
                    *(uint32_t*)(Clo + row * (long)N + col) = packbf(l0, l1);
                } else {
                    float2 o; o.x = v0; o.y = v1;
                    *(float2*)(C + row * (long)N + col) = o;
                }
            }
        }
    }
}

// ================= elementwise kernels =================
__global__ void rmsnorm_hilo_k(const float* __restrict__ x, const float* __restrict__ w,
                               __nv_bfloat16* __restrict__ hi, __nv_bfloat16* __restrict__ lo) {
    const long row = blockIdx.x;
    const float* xr = x + row * (long)Dn;
    const int t4 = threadIdx.x * 4;
    float4 v = *(const float4*)(xr + t4);
    float ss = v.x*v.x + v.y*v.y + v.z*v.z + v.w*v.w;
    #pragma unroll
    for (int o = 16; o > 0; o >>= 1) ss += __shfl_xor_sync(0xffffffffu, ss, o);
    __shared__ float warps[8];
    if ((threadIdx.x & 31) == 0) warps[threadIdx.x >> 5] = ss;
    __syncthreads();
    float tot = 0.f;
    #pragma unroll
    for (int i = 0; i < 8; i++) tot += warps[i];
    const float inv = rsqrtf(tot * (1.0f / Dn) + 1.1920929e-07f);
    float4 wv = *(const float4*)(w + t4);
    float o0 = v.x*inv*wv.x, o1 = v.y*inv*wv.y, o2 = v.z*inv*wv.z, o3 = v.w*inv*wv.w;
    __nv_bfloat16 h0,l0,h1,l1,h2,l2,h3,l3;
    split2(o0,h0,l0); split2(o1,h1,l1); split2(o2,h2,l2); split2(o3,h3,l3);
    uint2 hv; hv.x = packbf(h0,h1); hv.y = packbf(h2,h3);
    uint2 lv; lv.x = packbf(l0,l1); lv.y = packbf(l2,l3);
    *(uint2*)(hi + row * (long)Dn + t4) = hv;
    *(uint2*)(lo + row * (long)Dn + t4) = lv;
}

__global__ void split_k(const float* __restrict__ x, __nv_bfloat16* __restrict__ hi,
                        __nv_bfloat16* __restrict__ lo, long n4) {
    const long i = ((long)blockIdx.x * 256 + threadIdx.x);
    if (i >= n4) return;
    float4 v = *(const float4*)(x + i * 4);
    __nv_bfloat16 h0,l0,h1,l1,h2,l2,h3,l3;
    split2(v.x,h0,l0); split2(v.y,h1,l1); split2(v.z,h2,l2); split2(v.w,h3,l3);
    uint2 hv; hv.x = packbf(h0,h1); hv.y = packbf(h2,h3);
    uint2 lv; lv.x = packbf(l0,l1); lv.y = packbf(l2,l3);
    *(uint2*)(hi + i * 4) = hv;
    *(uint2*)(lo + i * 4) = lv;
}

__global__ void conv_kernel(const float* __restrict__ b1, const float* __restrict__ cbuf,
                            const float* __restrict__ cw, const float* __restrict__ cb,
                            float* __restrict__ out, __nv_bfloat16* __restrict__ hi,
                            __nv_bfloat16* __restrict__ lo) {
    const long idx = (long)blockIdx.x * 256 + threadIdx.x;
    if (idx >= BTD) return;
    const int d = (int)(idx % Dn);
    const long td = idx / Dn;
    const int t = (int)(td % Tn);
    const int b = (int)(td / Tn);
    float acc = cb[d];
    #pragma unroll
    for (int k = 0; k < CONVK; k++) {
        const int tt = t + k - (CONVK - 1);
        float v = (tt >= 0) ? b1[((long)b * Tn + tt) * Dn + d]
                            : cbuf[((long)b * (CONVK - 1) + (t + k)) * Dn + d];
        acc = fmaf(v, cw[d * CONVK + k], acc);
    }
    out[idx] = acc;
    __nv_bfloat16 h, l; split2(acc, h, l);
    hi[idx] = h; lo[idx] = l;
}

__global__ void gate_k(const float* __restrict__ r, float* __restrict__ ia,
                       const float* __restrict__ conv, const float* __restrict__ ll,
                       float* __restrict__ u) {
    const long idx = (long)blockIdx.x * 256 + threadIdx.x;
    if (idx >= BTD) return;
    const int d = (int)(idx % Dn);
    const float lam = ll[d];
    const float ls = -log1pf(expf(-lam));
    const float a = expf(8.0f * r[idx] * ls);
    const float gate = sqrtf(fmaxf((1.f - a) * (1.f + a), 1e-6f));
    const float uu = gate * ia[idx] * conv[idx];
    ia[idx] = a;
    u[idx] = uu;
}

__global__ void scan_k(const float* __restrict__ a, const float* __restrict__ u,
                       const float* __restrict__ h0, float* __restrict__ out,
                       float* __restrict__ newh) {
    const int idx = blockIdx.x * 256 + threadIdx.x;
    const int b = idx / Dn, d = idx % Dn;
    const long base = (long)b * Tn * Dn + d;
    float h = h0[idx];
    #pragma unroll 4
    for (int t = 0; t < Tn; t++) {
        const long o = base + (long)t * Dn;
        h = fmaf(a[o], h, u[o]);
        out[o] = h;
    }
    newh[idx] = h;
}

__global__ void mul_hilo_k(const float* __restrict__ x, const float* __restrict__ y,
                           __nv_bfloat16* __restrict__ hi, __nv_bfloat16* __restrict__ lo) {
    const long i = ((long)blockIdx.x * 256 + threadIdx.x);
    if (i >= BTD / 4) return;
    float4 a = *(const float4*)(x + i * 4);
    float4 b = *(const float4*)(y + i * 4);
    float v0 = a.x*b.x, v1 = a.y*b.y, v2 = a.z*b.z, v3 = a.w*b.w;
    __nv_bfloat16 h0,l0,h1,l1,h2,l2,h3,l3;
    split2(v0,h0,l0); split2(v1,h1,l1); split2(v2,h2,l2); split2(v3,h3,l3);
    uint2 hv; hv.x = packbf(h0,h1); hv.y = packbf(h2,h3);
    uint2 lv; lv.x = packbf(l0,l1); lv.y = packbf(l2,l3);
    *(uint2*)(hi + i * 4) = hv;
    *(uint2*)(lo + i * 4) = lv;
}

__global__ void cbuf_k(const float* __restrict__ b1, float* __restrict__ out) {
    const int idx = blockIdx.x * 256 + threadIdx.x;
    if (idx >= Bsz * (CONVK - 1) * Dn) return;
    const int d = idx % Dn;
    const int j = (idx / Dn) % (CONVK - 1);
    const int b = idx / (Dn * (CONVK - 1));
    out[idx] = b1[((long)b * Tn + (Tn - (CONVK - 1) + j)) * Dn + d];
}

// ================= host side =================
extern "C" void kernel_launch(void* const* d_in, const int* in_sizes, int n_in,
                              void* d_out, int out_size) {
    const float* x_seq   = (const float*)d_in[0];
    const float* h0      = (const float*)d_in[1];
    const float* convbuf = (const float*)d_in[2];
    const float* norm1_w = (const float*)d_in[3];
    const float* W1      = (const float*)d_in[4];
    const float* conv_w  = (const float*)d_in[5];
    const float* conv_b  = (const float*)d_in[6];
    const float* Wa      = (const float*)d_in[7];
    const float* ba      = (const float*)d_in[8];
    const float* Wx      = (const float*)d_in[9];
    const float* bx      = (const float*)d_in[10];
    const float* log_lam = (const float*)d_in[11];
    const float* W2      = (const float*)d_in[12];
    const float* Wout    = (const float*)d_in[13];
    const float* norm2_w = (const float*)d_in[14];
    const float* Wg      = (const float*)d_in[15];
    const float* Wu      = (const float*)d_in[16];
    const float* Wo      = (const float*)d_in[17];

    float* out_x2 = (float*)d_out;
    float* out_h  = out_x2 + (long)BTD;
    float* out_cb = out_h + (long)Bsz * Dn;

    float *p_b1, *p_conv, *p_r, *p_i, *p_u, *p_scan, *p_b2, *p_x1, *p_gl;
    cudaGetSymbolAddress((void**)&p_b1, g_b1);
    cudaGetSymbolAddress((void**)&p_conv, g_conv);
    cudaGetSymbolAddress((void**)&p_r, g_r);
    cudaGetSymbolAddress((void**)&p_i, g_i);
    cudaGetSymbolAddress((void**)&p_u, g_u);
    cudaGetSymbolAddress((void**)&p_scan, g_scan);
    cudaGetSymbolAddress((void**)&p_b2, g_b2);
    cudaGetSymbolAddress((void**)&p_x1, g_x1);
    cudaGetSymbolAddress((void**)&p_gl, g_gl);

    __nv_bfloat16 *nh,*nl,*ch,*cl,*ph,*pl,*n2h,*n2l,*acth,*actl;
    cudaGetSymbolAddress((void**)&nh, g_norm_h); cudaGetSymbolAddress((void**)&nl, g_norm_l);
    cudaGetSymbolAddress((void**)&ch, g_conv_h); cudaGetSymbolAddress((void**)&cl, g_conv_l);
    cudaGetSymbolAddress((void**)&ph, g_prod_h); cudaGetSymbolAddress((void**)&pl, g_prod_l);
    cudaGetSymbolAddress((void**)&n2h, g_n2_h);  cudaGetSymbolAddress((void**)&n2l, g_n2_l);
    cudaGetSymbolAddress((void**)&acth, g_act_h); cudaGetSymbolAddress((void**)&actl, g_act_l);

    __nv_bfloat16 *w1h,*w1l,*wah,*wal,*wxh,*wxl,*w2h,*w2l,*woh,*wol,*wgh,*wgl,*wuh,*wul,*wo2h,*wo2l;
    cudaGetSymbolAddress((void**)&w1h, g_w1_h);   cudaGetSymbolAddress((void**)&w1l, g_w1_l);
    cudaGetSymbolAddress((void**)&wah, g_wa_h);   cudaGetSymbolAddress((void**)&wal, g_wa_l);
    cudaGetSymbolAddress((void**)&wxh, g_wx_h);   cudaGetSymbolAddress((void**)&wxl, g_wx_l);
    cudaGetSymbolAddress((void**)&w2h, g_w2_h);   cudaGetSymbolAddress((void**)&w2l, g_w2_l);
    cudaGetSymbolAddress((void**)&woh, g_wo_h);   cudaGetSymbolAddress((void**)&wol, g_wo_l);
    cudaGetSymbolAddress((void**)&wgh, g_wg_h);   cudaGetSymbolAddress((void**)&wgl, g_wg_l);
    cudaGetSymbolAddress((void**)&wuh, g_wu_h);   cudaGetSymbolAddress((void**)&wul, g_wu_l);
    cudaGetSymbolAddress((void**)&wo2h, g_wout2_h); cudaGetSymbolAddress((void**)&wo2l, g_wout2_l);

    cudaFuncSetAttribute(gemm_mma<0,0>, cudaFuncAttributeMaxDynamicSharedMemorySize, SMEM_BYTES);
    cudaFuncSetAttribute(gemm_mma<1,0>, cudaFuncAttributeMaxDynamicSharedMemorySize, SMEM_BYTES);
    cudaFuncSetAttribute(gemm_mma<2,0>, cudaFuncAttributeMaxDynamicSharedMemorySize, SMEM_BYTES);
    cudaFuncSetAttribute(gemm_mma<3,0>, cudaFuncAttributeMaxDynamicSharedMemorySize, SMEM_BYTES);
    cudaFuncSetAttribute(gemm_mma<4,1>, cudaFuncAttributeMaxDynamicSharedMemorySize, SMEM_BYTES);

    const dim3 gD(Dn / 128, BT / 128);    // (8, 128)
    const dim3 gH(Hn / 128, BT / 128);    // (32, 128)
    const int EW = (BTD + 255) / 256;

    // weight hi/lo conversion
    split_k<<<(Dn*Dn/4 + 255)/256, 256>>>(W1,   w1h, w1l, Dn*Dn/4);
    split_k<<<(Dn*Dn/4 + 255)/256, 256>>>(Wa,   wah, wal, Dn*Dn/4);
    split_k<<<(Dn*Dn/4 + 255)/256, 256>>>(Wx,   wxh, wxl, Dn*Dn/4);
    split_k<<<(Dn*Dn/4 + 255)/256, 256>>>(W2,   w2h, w2l, Dn*Dn/4);
    split_k<<<(Dn*Dn/4 + 255)/256, 256>>>(Wout, woh, wol, Dn*Dn/4);
    split_k<<<((long)Hn*Dn/4 + 255)/256, 256>>>(Wg, wgh, wgl, (long)Hn*Dn/4);
    split_k<<<((long)Hn*Dn/4 + 255)/256, 256>>>(Wu, wuh, wul, (long)Hn*Dn/4);
    split_k<<<((long)Dn*Hn/4 + 255)/256, 256>>>(Wo, wo2h, wo2l, (long)Dn*Hn/4);

    // 1. rmsnorm1 -> hi/lo
    rmsnorm_hilo_k<<<BT, 256>>>(x_seq, norm1_w, nh, nl);
    // 2. b1 = normed @ W1^T
    gemm_mma<0,0><<<gD, 256, SMEM_BYTES>>>(nh, nl, w1h, w1l, p_b1, nullptr, nullptr,
                                           nullptr, nullptr, Dn, Dn);
    // 3. conv (+hi/lo) and new_conv_buf
    conv_kernel<<<EW, 256>>>(p_b1, convbuf, conv_w, conv_b, p_conv, ch, cl);
    cbuf_k<<<(Bsz * (CONVK - 1) * Dn + 255) / 256, 256>>>(p_b1, out_cb);
    // 4/5. r, i = sigmoid(conv @ {Wa,Wx}^T + {ba,bx})
    gemm_mma<1,0><<<gD, 256, SMEM_BYTES>>>(ch, cl, wah, wal, p_r, nullptr, nullptr,
                                           nullptr, ba, Dn, Dn);
    gemm_mma<1,0><<<gD, 256, SMEM_BYTES>>>(ch, cl, wxh, wxl, p_i, nullptr, nullptr,
                                           nullptr, bx, Dn, Dn);
    // 6. a, u
    gate_k<<<EW, 256>>>(p_r, p_i, p_conv, log_lam, p_u);
    // 7. scan
    scan_k<<<(Bsz * Dn) / 256, 256>>>(p_i, p_u, h0, p_scan, out_h);
    // 8. b2 = gelu(normed @ W2^T)
    gemm_mma<2,0><<<gD, 256, SMEM_BYTES>>>(nh, nl, w2h, w2l, p_b2, nullptr, nullptr,
                                           nullptr, nullptr, Dn, Dn);
    // 9. prod = b2 * scan -> hi/lo
    mul_hilo_k<<<(BTD/4 + 255)/256, 256>>>(p_b2, p_scan, ph, pl);
    // 10. x1 = x_seq + prod @ Wout^T
    gemm_mma<3,0><<<gD, 256, SMEM_BYTES>>>(ph, pl, woh, wol, p_x1, nullptr, nullptr,
                                           x_seq, nullptr, Dn, Dn);
    // 11. n2 = rmsnorm(x1) -> hi/lo
    rmsnorm_hilo_k<<<BT, 256>>>(p_x1, norm2_w, n2h, n2l);
    // 12. gl = gelu(n2 @ Wg^T)
    gemm_mma<2,0><<<gH, 256, SMEM_BYTES>>>(n2h, n2l, wgh, wgl, p_gl, nullptr, nullptr,
                                           nullptr, nullptr, Hn, Dn);
    // 13. act = (n2 @ Wu^T) * gl -> hi/lo
    gemm_mma<4,1><<<gH, 256, SMEM_BYTES>>>(n2h, n2l, wuh, wul, nullptr, acth, actl,
                                           p_gl, nullptr, Hn, Dn);
    // 14. x2 = x1 + act @ Wo^T
    gemm_mma<3,0><<<gD, 256, SMEM_BYTES>>>(acth, actl, wo2h, wo2l, out_x2, nullptr, nullptr,
                                           p_x1, nullptr, Dn, Hn);
}

// round 4
// speedup vs baseline: 4.6872x; 2.3308x over previous
#include <cuda_runtime.h>
#include <cuda_fp16.h>
#include <math.h>
#include <stdint.h>

// ---------------- problem dims ----------------
#define Bsz 16
#define Tn  1024
#define Dn  1024
#define Hn  4096
#define BT  (Bsz*Tn)              // 16384
#define BTD (Bsz*Tn*Dn)           // 16777216
#define BTH (Bsz*Tn*Hn)           // 67108864
#define CONVK 4

// ---------------- GEMM tile config ----------------
#define STAGES 4
#define TILE_BYTES  10240         // 128 rows x 80B (stride 40 fp16)
#define STAGE_BYTES 20480         // A, B
#define SMEM_BYTES  (STAGES*STAGE_BYTES)   // 81920 -> 2 CTAs/SM

// ---------------- scratch (device globals) ----------------
__device__ __align__(128) float g_b1[BTD];
__device__ __align__(128) float g_conv[BTD];
__device__ __align__(128) float g_r[BTD];
__device__ __align__(128) float g_i[BTD];
__device__ __align__(128) float g_scan[BTD];
__device__ __align__(128) float g_b2[BTD];
__device__ __align__(128) float g_x1[BTD];
__device__ __align__(128) float g_gl[BTH];

__device__ __align__(128) __half g_norm_h[BTD];
__device__ __align__(128) __half g_conv_h[BTD];
__device__ __align__(128) __half g_prod_h[BTD];
__device__ __align__(128) __half g_n2_h[BTD];
__device__ __align__(128) __half g_act_h[BTH];

__device__ __align__(128) __half g_w1_h[Dn*Dn];
__device__ __align__(128) __half g_wa_h[Dn*Dn];
__device__ __align__(128) __half g_wx_h[Dn*Dn];
__device__ __align__(128) __half g_w2_h[Dn*Dn];
__device__ __align__(128) __half g_wo_h[Dn*Dn];              // Wout
__device__ __align__(128) __half g_wg_h[(long)Hn*Dn];
__device__ __align__(128) __half g_wu_h[(long)Hn*Dn];
__device__ __align__(128) __half g_wout2_h[(long)Dn*Hn];     // Wo

// ---------------- helpers ----------------
__device__ __forceinline__ uint32_t smem_u32(const void* p) {
    uint32_t a;
    asm("{ .reg .u64 t; cvta.to.shared.u64 t, %1; cvt.u32.u64 %0, t; }"
        : "=r"(a) : "l"(p));
    return a;
}
__device__ __forceinline__ float gelu_f(float x) {
    return 0.5f * x * (1.0f + erff(x * 0.70710678118654752440f));
}
__device__ __forceinline__ float sigm_f(float x) {
    return 1.0f / (1.0f + expf(-x));
}
__device__ __forceinline__ uint32_t pack2h(float a, float b) {
    __half2 t = __floats2half2_rn(a, b);
    return *reinterpret_cast<uint32_t*>(&t);
}
__device__ __forceinline__ void ldsm4(uint32_t addr, uint32_t r[4]) {
    asm volatile("ldmatrix.sync.aligned.m8n8.x4.shared.b16 {%0,%1,%2,%3}, [%4];"
                 : "=r"(r[0]), "=r"(r[1]), "=r"(r[2]), "=r"(r[3]) : "r"(addr));
}
__device__ __forceinline__ void mma16816(float c[4], const uint32_t a[4], const uint32_t b[2]) {
    asm volatile("mma.sync.aligned.m16n8k16.row.col.f32.f16.f16.f32 "
                 "{%0,%1,%2,%3}, {%4,%5,%6,%7}, {%8,%9}, {%0,%1,%2,%3};"
                 : "+f"(c[0]), "+f"(c[1]), "+f"(c[2]), "+f"(c[3])
                 : "r"(a[0]), "r"(a[1]), "r"(a[2]), "r"(a[3]), "r"(b[0]), "r"(b[1]));
}
__device__ __forceinline__ void cp16(uint32_t dst, const void* src) {
    asm volatile("cp.async.cg.shared.global [%0], [%1], 16;" :: "r"(dst), "l"(src));
}
#define CP_COMMIT() asm volatile("cp.async.commit_group;" ::: "memory")
#define CP_WAIT2()  asm volatile("cp.async.wait_group 2;" ::: "memory")

// ================= GEMM: C[M,N] = A[M,K] @ B[N,K]^T (fp16 in, f32 acc) ======
// EPI: 0=none 1=sigmoid(v+bias[col]) 2=gelu 3=v+aux 4=v*aux
// HOUT: 1 -> write __half to Ch instead of float C
template<int EPI, int HOUT>
__global__ void __launch_bounds__(256, 2)
gemm_mma(const __half* __restrict__ A, const __half* __restrict__ B,
         float* __restrict__ C, __half* __restrict__ Ch,
         const float* __restrict__ aux, const float* __restrict__ bias,
         int N, int K)
{
    extern __shared__ __align__(128) char smem[];
    const uint32_t sb = smem_u32(smem);
    const int tid = threadIdx.x;
    const int lane = tid & 31, wid = tid >> 5;
    const int wm = wid & 1;            // 2 warps along M (64 rows each)
    const int wn = wid >> 1;           // 4 warps along N (32 cols each)
    const long rowA = (long)blockIdx.y * 128;
    const long rowB = (long)blockIdx.x * 128;
    const int nk = K >> 5;             // BK = 32

    float acc[4][4][4];
    #pragma unroll
    for (int i = 0; i < 4; i++)
        #pragma unroll
        for (int n = 0; n < 4; n++)
            #pragma unroll
            for (int q = 0; q < 4; q++) acc[i][n][q] = 0.f;

    auto load_stage = [&](int s, int kt) {
        const uint32_t base = sb + s * STAGE_BYTES;
        const int k0 = kt << 5;
        #pragma unroll
        for (int t = 0; t < 2; t++) {
            const int idx = tid + t * 256;
            const int r = idx >> 2, c = idx & 3;
            cp16(base + r * 80 + c * 16, A + (rowA + r) * (long)K + k0 + c * 8);
            cp16(base + 10240 + r * 80 + c * 16, B + (rowB + r) * (long)K + k0 + c * 8);
        }
    };

    load_stage(0, 0); CP_COMMIT();
    load_stage(1, 1); CP_COMMIT();
    load_stage(2, 2); CP_COMMIT();

    for (int kt = 0; kt < nk; kt++) {
        CP_WAIT2();
        __syncthreads();
        if (kt + 3 < nk) load_stage((kt + 3) & 3, kt + 3);
        CP_COMMIT();

        const uint32_t base = sb + (kt & 3) * STAGE_BYTES;
        #pragma unroll
        for (int kk = 0; kk < 2; kk++) {
            const uint32_t koff = (kk * 16 + (lane >> 4) * 8) * 2;   // byte offset in row
            uint32_t ah[4][4];
            #pragma unroll
            for (int i = 0; i < 4; i++) {
                const uint32_t off = (uint32_t)(wm * 64 + i * 16 + (lane & 15)) * 80 + koff;
                ldsm4(base + off, ah[i]);
            }
            uint32_t bh[4][2];
            #pragma unroll
            for (int j = 0; j < 2; j++) {
                const uint32_t off = (uint32_t)(wn * 32 + j * 16 + (lane & 15)) * 80 + koff;
                uint32_t t[4];
                ldsm4(base + 10240 + off, t);
                bh[2*j][0] = t[0]; bh[2*j][1] = t[2];
                bh[2*j+1][0] = t[1]; bh[2*j+1][1] = t[3];
            }
            #pragma unroll
            for (int i = 0; i < 4; i++)
                #pragma unroll
                for (int n = 0; n < 4; n++)
                    mma16816(acc[i][n], ah[i], bh[n]);
        }
    }

    // ---- epilogue ----
    const long r0 = rowA + wm * 64 + (lane >> 2);
    const long c0 = rowB + wn * 32 + (lane & 3) * 2;
    #pragma unroll
    for (int i = 0; i < 4; i++) {
        #pragma unroll
        for (int n = 0; n < 4; n++) {
            #pragma unroll
            for (int h = 0; h < 2; h++) {
                const long row = r0 + i * 16 + h * 8;
                const long col = c0 + n * 8;
                float v0 = acc[i][n][2*h + 0];
                float v1 = acc[i][n][2*h + 1];
                if (EPI == 1) {
                    v0 = sigm_f(v0 + bias[col]);
                    v1 = sigm_f(v1 + bias[col + 1]);
                } else if (EPI == 2) {
                    v0 = gelu_f(v0); v1 = gelu_f(v1);
                } else if (EPI == 3) {
                    const float2 a2 = *(const float2*)(aux + row * (long)N + col);
                    v0 += a2.x; v1 += a2.y;
                } else if (EPI == 4) {
                    const float2 a2 = *(const float2*)(aux + row * (long)N + col);
                    v0 *= a2.x; v1 *= a2.y;
                }
                if (HOUT) {
                    *(uint32_t*)(Ch + row * (long)N + col) = pack2h(v0, v1);
                } else {
                    float2 o; o.x = v0; o.y = v1;
                    *(float2*)(C + row * (long)N + col) = o;
                }
            }
        }
    }
}

// ================= elementwise kernels =================
__global__ void rmsnorm_half_k(const float* __restrict__ x, const float* __restrict__ w,
                               __half* __restrict__ out) {
    const long row = blockIdx.x;
    const float* xr = x + row * (long)Dn;
    const int t4 = threadIdx.x * 4;
    float4 v = *(const float4*)(xr + t4);
    float ss = v.x*v.x + v.y*v.y + v.z*v.z + v.w*v.w;
    #pragma unroll
    for (int o = 16; o > 0; o >>= 1) ss += __shfl_xor_sync(0xffffffffu, ss, o);
    __shared__ float warps[8];
    if ((threadIdx.x & 31) == 0) warps[threadIdx.x >> 5] = ss;
    __syncthreads();
    float tot = 0.f;
    #pragma unroll
    for (int i = 0; i < 8; i++) tot += warps[i];
    const float inv = rsqrtf(tot * (1.0f / Dn) + 1.1920929e-07f);
    float4 wv = *(const float4*)(w + t4);
    uint2 hv;
    hv.x = pack2h(v.x*inv*wv.x, v.y*inv*wv.y);
    hv.y = pack2h(v.z*inv*wv.z, v.w*inv*wv.w);
    *(uint2*)(out + row * (long)Dn + t4) = hv;
}

__global__ void tohalf_k(const float* __restrict__ x, __half* __restrict__ out, long n4) {
    const long i = ((long)blockIdx.x * 256 + threadIdx.x);
    if (i >= n4) return;
    float4 v = *(const float4*)(x + i * 4);
    uint2 hv;
    hv.x = pack2h(v.x, v.y);
    hv.y = pack2h(v.z, v.w);
    *(uint2*)(out + i * 4) = hv;
}

__global__ void conv_kernel(const float* __restrict__ b1, const float* __restrict__ cbuf,
                            const float* __restrict__ cw, const float* __restrict__ cb,
                            float* __restrict__ out, __half* __restrict__ oh) {
    const long idx = (long)blockIdx.x * 256 + threadIdx.x;
    if (idx >= BTD) return;
    const int d = (int)(idx % Dn);
    const long td = idx / Dn;
    const int t = (int)(td % Tn);
    const int b = (int)(td / Tn);
    float acc = cb[d];
    #pragma unroll
    for (int k = 0; k < CONVK; k++) {
        const int tt = t + k - (CONVK - 1);
        float v = (tt >= 0) ? b1[((long)b * Tn + tt) * Dn + d]
                            : cbuf[((long)b * (CONVK - 1) + (t + k)) * Dn + d];
        acc = fmaf(v, cw[d * CONVK + k], acc);
    }
    out[idx] = acc;
    oh[idx] = __float2half_rn(acc);
}

// fused gate + scan: reads r, i, conv; computes a,u on the fly
__global__ void scan_fused_k(const float* __restrict__ r, const float* __restrict__ ig,
                             const float* __restrict__ conv, const float* __restrict__ ll,
                             const float* __restrict__ h0, float* __restrict__ out,
                             float* __restrict__ newh) {
    const int idx = blockIdx.x * 256 + threadIdx.x;
    const int b = idx / Dn, d = idx % Dn;
    const float lam = ll[d];
    const float ls8 = -8.0f * log1pf(expf(-lam));   // 8 * log_sigmoid(lambda)
    const long base = (long)b * Tn * Dn + d;
    float h = h0[idx];
    #pragma unroll 4
    for (int t = 0; t < Tn; t++) {
        const long o = base + (long)t * Dn;
        const float a = expf(r[o] * ls8);
        const float gate = sqrtf(fmaxf((1.f - a) * (1.f + a), 1e-6f));
        const float u = gate * ig[o] * conv[o];
        h = fmaf(a, h, u);
        out[o] = h;
    }
    newh[idx] = h;
}

__global__ void mul_half_k(const float* __restrict__ x, const float* __restrict__ y,
                           __half* __restrict__ out) {
    const long i = ((long)blockIdx.x * 256 + threadIdx.x);
    if (i >= BTD / 4) return;
    float4 a = *(const float4*)(x + i * 4);
    float4 b = *(const float4*)(y + i * 4);
    uint2 hv;
    hv.x = pack2h(a.x*b.x, a.y*b.y);
    hv.y = pack2h(a.z*b.z, a.w*b.w);
    *(uint2*)(out + i * 4) = hv;
}

__global__ void cbuf_k(const float* __restrict__ b1, float* __restrict__ out) {
    const int idx = blockIdx.x * 256 + threadIdx.x;
    if (idx >= Bsz * (CONVK - 1) * Dn) return;
    const int d = idx % Dn;
    const int j = (idx / Dn) % (CONVK - 1);
    const int b = idx / (Dn * (CONVK - 1));
    out[idx] = b1[((long)b * Tn + (Tn - (CONVK - 1) + j)) * Dn + d];
}

// ================= host side =================
extern "C" void kernel_launch(void* const* d_in, const int* in_sizes, int n_in,
                              void* d_out, int out_size) {
    const float* x_seq   = (const float*)d_in[0];
    const float* h0      = (const float*)d_in[1];
    const float* convbuf = (const float*)d_in[2];
    const float* norm1_w = (const float*)d_in[3];
    const float* W1      = (const float*)d_in[4];
    const float* conv_w  = (const float*)d_in[5];
    const float* conv_b  = (const float*)d_in[6];
    const float* Wa      = (const float*)d_in[7];
    const float* ba      = (const float*)d_in[8];
    const float* Wx      = (const float*)d_in[9];
    const float* bx      = (const float*)d_in[10];
    const float* log_lam = (const float*)d_in[11];
    const float* W2      = (const float*)d_in[12];
    const float* Wout    = (const float*)d_in[13];
    const float* norm2_w = (const float*)d_in[14];
    const float* Wg      = (const float*)d_in[15];
    const float* Wu      = (const float*)d_in[16];
    const float* Wo      = (const float*)d_in[17];

    float* out_x2 = (float*)d_out;
    float* out_h  = out_x2 + (long)BTD;
    float* out_cb = out_h + (long)Bsz * Dn;

    float *p_b1, *p_conv, *p_r, *p_i, *p_scan, *p_b2, *p_x1, *p_gl;
    cudaGetSymbolAddress((void**)&p_b1, g_b1);
    cudaGetSymbolAddress((void**)&p_conv, g_conv);
    cudaGetSymbolAddress((void**)&p_r, g_r);
    cudaGetSymbolAddress((void**)&p_i, g_i);
    cudaGetSymbolAddress((void**)&p_scan, g_scan);
    cudaGetSymbolAddress((void**)&p_b2, g_b2);
    cudaGetSymbolAddress((void**)&p_x1, g_x1);
    cudaGetSymbolAddress((void**)&p_gl, g_gl);

    __half *nh, *ch, *ph, *n2h, *acth;
    cudaGetSymbolAddress((void**)&nh, g_norm_h);
    cudaGetSymbolAddress((void**)&ch, g_conv_h);
    cudaGetSymbolAddress((void**)&ph, g_prod_h);
    cudaGetSymbolAddress((void**)&n2h, g_n2_h);
    cudaGetSymbolAddress((void**)&acth, g_act_h);

    __half *w1h, *wah, *wxh, *w2h, *woh, *wgh, *wuh, *wo2h;
    cudaGetSymbolAddress((void**)&w1h, g_w1_h);
    cudaGetSymbolAddress((void**)&wah, g_wa_h);
    cudaGetSymbolAddress((void**)&wxh, g_wx_h);
    cudaGetSymbolAddress((void**)&w2h, g_w2_h);
    cudaGetSymbolAddress((void**)&woh, g_wo_h);
    cudaGetSymbolAddress((void**)&wgh, g_wg_h);
    cudaGetSymbolAddress((void**)&wuh, g_wu_h);
    cudaGetSymbolAddress((void**)&wo2h, g_wout2_h);

    cudaFuncSetAttribute(gemm_mma<0,0>, cudaFuncAttributeMaxDynamicSharedMemorySize, SMEM_BYTES);
    cudaFuncSetAttribute(gemm_mma<1,0>, cudaFuncAttributeMaxDynamicSharedMemorySize, SMEM_BYTES);
    cudaFuncSetAttribute(gemm_mma<2,0>, cudaFuncAttributeMaxDynamicSharedMemorySize, SMEM_BYTES);
    cudaFuncSetAttribute(gemm_mma<3,0>, cudaFuncAttributeMaxDynamicSharedMemorySize, SMEM_BYTES);
    cudaFuncSetAttribute(gemm_mma<4,1>, cudaFuncAttributeMaxDynamicSharedMemorySize, SMEM_BYTES);

    const dim3 gD(Dn / 128, BT / 128);    // (8, 128)
    const dim3 gH(Hn / 128, BT / 128);    // (32, 128)
    const int EW = (BTD + 255) / 256;

    // weight fp16 conversion
    tohalf_k<<<(Dn*Dn/4 + 255)/256, 256>>>(W1,   w1h, Dn*Dn/4);
    tohalf_k<<<(Dn*Dn/4 + 255)/256, 256>>>(Wa,   wah, Dn*Dn/4);
    tohalf_k<<<(Dn*Dn/4 + 255)/256, 256>>>(Wx,   wxh, Dn*Dn/4);
    tohalf_k<<<(Dn*Dn/4 + 255)/256, 256>>>(W2,   w2h, Dn*Dn/4);
    tohalf_k<<<(Dn*Dn/4 + 255)/256, 256>>>(Wout, woh, Dn*Dn/4);
    tohalf_k<<<((long)Hn*Dn/4 + 255)/256, 256>>>(Wg, wgh, (long)Hn*Dn/4);
    tohalf_k<<<((long)Hn*Dn/4 + 255)/256, 256>>>(Wu, wuh, (long)Hn*Dn/4);
    tohalf_k<<<((long)Dn*Hn/4 + 255)/256, 256>>>(Wo, wo2h, (long)Dn*Hn/4);

    // 1. rmsnorm1 -> fp16
    rmsnorm_half_k<<<BT, 256>>>(x_seq, norm1_w, nh);
    // 2. b1 = normed @ W1^T
    gemm_mma<0,0><<<gD, 256, SMEM_BYTES>>>(nh, w1h, p_b1, nullptr, nullptr, nullptr, Dn, Dn);
    // 3. conv (+fp16) and new_conv_buf
    conv_kernel<<<EW, 256>>>(p_b1, convbuf, conv_w, conv_b, p_conv, ch);
    cbuf_k<<<(Bsz * (CONVK - 1) * Dn + 255) / 256, 256>>>(p_b1, out_cb);
    // 4/5. r, i = sigmoid(conv @ {Wa,Wx}^T + {ba,bx})
    gemm_mma<1,0><<<gD, 256, SMEM_BYTES>>>(ch, wah, p_r, nullptr, nullptr, ba, Dn, Dn);
    gemm_mma<1,0><<<gD, 256, SMEM_BYTES>>>(ch, wxh, p_i, nullptr, nullptr, bx, Dn, Dn);
    // 6. fused gate + scan
    scan_fused_k<<<(Bsz * Dn) / 256, 256>>>(p_r, p_i, p_conv, log_lam, h0, p_scan, out_h);
    // 7. b2 = gelu(normed @ W2^T)
    gemm_mma<2,0><<<gD, 256, SMEM_BYTES>>>(nh, w2h, p_b2, nullptr, nullptr, nullptr, Dn, Dn);
    // 8. prod = b2 * scan -> fp16
    mul_half_k<<<(BTD/4 + 255)/256, 256>>>(p_b2, p_scan, ph);
    // 9. x1 = x_seq + prod @ Wout^T
    gemm_mma<3,0><<<gD, 256, SMEM_BYTES>>>(ph, woh, p_x1, nullptr, x_seq, nullptr, Dn, Dn);
    // 10. n2 = rmsnorm(x1) -> fp16
    rmsnorm_half_k<<<BT, 256>>>(p_x1, norm2_w, n2h);
    // 11. gl = gelu(n2 @ Wg^T)
    gemm_mma<2,0><<<gH, 256, SMEM_BYTES>>>(n2h, wgh, p_gl, nullptr, nullptr, nullptr, Hn, Dn);
    // 12. act = (n2 @ Wu^T) * gl -> fp16
    gemm_mma<4,1><<<gH, 256, SMEM_BYTES>>>(n2h, wuh, nullptr, acth, p_gl, nullptr, Hn, Dn);
    // 13. x2 = x1 + act @ Wo^T
    gemm_mma<3,0><<<gD, 256, SMEM_BYTES>>>(acth, wo2h, out_x2, nullptr, p_x1, nullptr, Dn, Hn);
}

// round 6
// speedup vs baseline: 5.3346x; 1.1381x over previous
#include <cuda_runtime.h>
#include <cuda_fp16.h>
#include <math.h>
#include <stdint.h>

// ---------------- problem dims ----------------
#define Bsz 16
#define Tn  1024
#define Dn  1024
#define Hn  4096
#define BT  (Bsz*Tn)              // 16384
#define BTD (Bsz*Tn*Dn)           // 16777216
#define BTH (Bsz*Tn*Hn)           // 67108864
#define CONVK 4

// ---------------- GEMM tile config (single: 256x128, dual: 128x128) --------
#define STAGES 4
// single: A 256x32 fp16 @80B stride = 20480B, B 128x32 = 10240B
#define S_A_BYTES 20480
#define S_STAGE   30720
#define S_SMEM    (STAGES*S_STAGE)    // 122880
// dual: A 128x32 = 10240B, Bg 10240, Bu 10240
#define D_STAGE   30720
#define D_SMEM    (STAGES*D_STAGE)    // 122880

// ---------------- scratch (device globals) ----------------
__device__ __align__(128) float g_b1[BTD];
__device__ __align__(128) float g_conv[BTD];
__device__ __align__(128) float g_r[BTD];
__device__ __align__(128) float g_i[BTD];
__device__ __align__(128) float g_scan[BTD];
__device__ __align__(128) float g_x1[BTD];

__device__ __align__(128) __half g_norm_h[BTD];
__device__ __align__(128) __half g_conv_h[BTD];
__device__ __align__(128) __half g_prod_h[BTD];
__device__ __align__(128) __half g_n2_h[BTD];
__device__ __align__(128) __half g_act_h[BTH];

__device__ __align__(128) __half g_w1_h[Dn*Dn];
__device__ __align__(128) __half g_wa_h[Dn*Dn];
__device__ __align__(128) __half g_wx_h[Dn*Dn];
__device__ __align__(128) __half g_w2_h[Dn*Dn];
__device__ __align__(128) __half g_wo_h[Dn*Dn];              // Wout
__device__ __align__(128) __half g_wg_h[(long)Hn*Dn];
__device__ __align__(128) __half g_wu_h[(long)Hn*Dn];
__device__ __align__(128) __half g_wout2_h[(long)Dn*Hn];     // Wo

// ---------------- helpers ----------------
__device__ __forceinline__ uint32_t smem_u32(const void* p) {
    uint32_t a;
    asm("{ .reg .u64 t; cvta.to.shared.u64 t, %1; cvt.u32.u64 %0, t; }"
        : "=r"(a) : "l"(p));
    return a;
}
__device__ __forceinline__ float gelu_f(float x) {
    return 0.5f * x * (1.0f + erff(x * 0.70710678118654752440f));
}
__device__ __forceinline__ float sigm_f(float x) {
    return 1.0f / (1.0f + expf(-x));
}
__device__ __forceinline__ uint32_t pack2h(float a, float b) {
    __half2 t = __floats2half2_rn(a, b);
    return *reinterpret_cast<uint32_t*>(&t);
}
__device__ __forceinline__ void ldsm4(uint32_t addr, uint32_t r[4]) {
    asm volatile("ldmatrix.sync.aligned.m8n8.x4.shared.b16 {%0,%1,%2,%3}, [%4];"
                 : "=r"(r[0]), "=r"(r[1]), "=r"(r[2]), "=r"(r[3]) : "r"(addr));
}
__device__ __forceinline__ void mma16816(float c[4], const uint32_t a[4], const uint32_t b[2]) {
    asm volatile("mma.sync.aligned.m16n8k16.row.col.f32.f16.f16.f32 "
                 "{%0,%1,%2,%3}, {%4,%5,%6,%7}, {%8,%9}, {%0,%1,%2,%3};"
                 : "+f"(c[0]), "+f"(c[1]), "+f"(c[2]), "+f"(c[3])
                 : "r"(a[0]), "r"(a[1]), "r"(a[2]), "r"(a[3]), "r"(b[0]), "r"(b[1]));
}
__device__ __forceinline__ void cp16(uint32_t dst, const void* src) {
    asm volatile("cp.async.cg.shared.global [%0], [%1], 16;" :: "r"(dst), "l"(src));
}
#define CP_COMMIT() asm volatile("cp.async.commit_group;" ::: "memory")
#define CP_WAIT2()  asm volatile("cp.async.wait_group 2;" ::: "memory")

// ================= GEMM 256x128: C[M,N] = A[M,K] @ B[N,K]^T =================
// EPI: 0=none 1=sigmoid(v+bias[col]) 2=gelu 3=v+aux 5=gelu(v)*aux
// HOUT: 1 -> write __half to Ch
template<int EPI, int HOUT>
__global__ void __launch_bounds__(256, 1)
gemm_mma(const __half* __restrict__ A, const __half* __restrict__ B,
         float* __restrict__ C, __half* __restrict__ Ch,
         const float* __restrict__ aux, const float* __restrict__ bias,
         int N, int K)
{
    extern __shared__ __align__(128) char smem[];
    const uint32_t sb = smem_u32(smem);
    const int tid = threadIdx.x;
    const int lane = tid & 31, wid = tid >> 5;
    const int wm = wid & 3;            // 4 warps along M (64 rows each)
    const int wn = wid >> 2;           // 2 warps along N (64 cols each)
    const long rowA = (long)blockIdx.y * 256;
    const long rowB = (long)blockIdx.x * 128;
    const int nk = K >> 5;             // BK = 32

    float acc[4][8][4];
    #pragma unroll
    for (int i = 0; i < 4; i++)
        #pragma unroll
        for (int n = 0; n < 8; n++)
            #pragma unroll
            for (int q = 0; q < 4; q++) acc[i][n][q] = 0.f;

    auto load_stage = [&](int s, int kt) {
        const uint32_t base = sb + s * S_STAGE;
        const int k0 = kt << 5;
        #pragma unroll
        for (int t = 0; t < 4; t++) {
            const int idx = tid + t * 256;
            const int r = idx >> 2, c = idx & 3;
            cp16(base + r * 80 + c * 16, A + (rowA + r) * (long)K + k0 + c * 8);
        }
        #pragma unroll
        for (int t = 0; t < 2; t++) {
            const int idx = tid + t * 256;
            const int r = idx >> 2, c = idx & 3;
            cp16(base + S_A_BYTES + r * 80 + c * 16, B + (rowB + r) * (long)K + k0 + c * 8);
        }
    };

    load_stage(0, 0); CP_COMMIT();
    load_stage(1, 1); CP_COMMIT();
    load_stage(2, 2); CP_COMMIT();

    for (int kt = 0; kt < nk; kt++) {
        CP_WAIT2();
        __syncthreads();
        if (kt + 3 < nk) load_stage((kt + 3) & 3, kt + 3);
        CP_COMMIT();

        const uint32_t base = sb + (kt & 3) * S_STAGE;
        #pragma unroll
        for (int kk = 0; kk < 2; kk++) {
            const uint32_t koff = (kk * 16 + (lane >> 4) * 8) * 2;   // byte offset
            uint32_t ah[4][4];
            #pragma unroll
            for (int i = 0; i < 4; i++) {
                const uint32_t off = (uint32_t)(wm * 64 + i * 16 + (lane & 15)) * 80 + koff;
                ldsm4(base + off, ah[i]);
            }
            uint32_t bh[8][2];
            #pragma unroll
            for (int j = 0; j < 4; j++) {
                const uint32_t off = (uint32_t)(wn * 64 + j * 16 + (lane & 15)) * 80 + koff;
                uint32_t t[4];
                ldsm4(base + S_A_BYTES + off, t);
                bh[2*j][0] = t[0]; bh[2*j][1] = t[2];
                bh[2*j+1][0] = t[1]; bh[2*j+1][1] = t[3];
            }
            #pragma unroll
            for (int i = 0; i < 4; i++)
                #pragma unroll
                for (int n = 0; n < 8; n++)
                    mma16816(acc[i][n], ah[i], bh[n]);
        }
    }

    // ---- epilogue ----
    const long r0 = rowA + wm * 64 + (lane >> 2);
    const long c0 = rowB + wn * 64 + (lane & 3) * 2;
    #pragma unroll
    for (int i = 0; i < 4; i++) {
        #pragma unroll
        for (int n = 0; n < 8; n++) {
            #pragma unroll
            for (int h = 0; h < 2; h++) {
                const long row = r0 + i * 16 + h * 8;
                const long col = c0 + n * 8;
                float v0 = acc[i][n][2*h + 0];
                float v1 = acc[i][n][2*h + 1];
                if (EPI == 1) {
                    v0 = sigm_f(v0 + bias[col]);
                    v1 = sigm_f(v1 + bias[col + 1]);
                } else if (EPI == 2) {
                    v0 = gelu_f(v0); v1 = gelu_f(v1);
                } else if (EPI == 3) {
                    const float2 a2 = *(const float2*)(aux + row * (long)N + col);
                    v0 += a2.x; v1 += a2.y;
                } else if (EPI == 5) {
                    const float2 a2 = *(const float2*)(aux + row * (long)N + col);
                    v0 = gelu_f(v0) * a2.x; v1 = gelu_f(v1) * a2.y;
                }
                if (HOUT) {
                    *(uint32_t*)(Ch + row * (long)N + col) = pack2h(v0, v1);
                } else {
                    float2 o; o.x = v0; o.y = v1;
                    *(float2*)(C + row * (long)N + col) = o;
                }
            }
        }
    }
}

// ================= Dual GEMM 128x128: act = gelu(A@Bg^T)*(A@Bu^T) -> fp16 ===
__global__ void __launch_bounds__(256, 1)
gemm_dual(const __half* __restrict__ A, const __half* __restrict__ Bg,
          const __half* __restrict__ Bu, __half* __restrict__ Ch,
          int N, int K)
{
    extern __shared__ __align__(128) char smem[];
    const uint32_t sb = smem_u32(smem);
    const int tid = threadIdx.x;
    const int lane = tid & 31, wid = tid >> 5;
    const int wm = wid & 1;            // 2 warps along M (64 rows)
    const int wn = wid >> 1;           // 4 warps along N (32 cols)
    const long rowA = (long)blockIdx.y * 128;
    const long rowB = (long)blockIdx.x * 128;
    const int nk = K >> 5;

    float accg[4][4][4], accu[4][4][4];
    #pragma unroll
    for (int i = 0; i < 4; i++)
        #pragma unroll
        for (int n = 0; n < 4; n++)
            #pragma unroll
            for (int q = 0; q < 4; q++) { accg[i][n][q] = 0.f; accu[i][n][q] = 0.f; }

    auto load_stage = [&](int s, int kt) {
        const uint32_t base = sb + s * D_STAGE;
        const int k0 = kt << 5;
        #pragma unroll
        for (int t = 0; t < 2; t++) {
            const int idx = tid + t * 256;
            const int r = idx >> 2, c = idx & 3;
            cp16(base + r * 80 + c * 16, A + (rowA + r) * (long)K + k0 + c * 8);
            cp16(base + 10240 + r * 80 + c * 16, Bg + (rowB + r) * (long)K + k0 + c * 8);
            cp16(base + 20480 + r * 80 + c * 16, Bu + (rowB + r) * (long)K + k0 + c * 8);
        }
    };

    load_stage(0, 0); CP_COMMIT();
    load_stage(1, 1); CP_COMMIT();
    load_stage(2, 2); CP_COMMIT();

    for (int kt = 0; kt < nk; kt++) {
        CP_WAIT2();
        __syncthreads();
        if (kt + 3 < nk) load_stage((kt + 3) & 3, kt + 3);
        CP_COMMIT();

        const uint32_t base = sb + (kt & 3) * D_STAGE;
        #pragma unroll
        for (int kk = 0; kk < 2; kk++) {
            const uint32_t koff = (kk * 16 + (lane >> 4) * 8) * 2;
            uint32_t ah[4][4];
            #pragma unroll
            for (int i = 0; i < 4; i++) {
                const uint32_t off = (uint32_t)(wm * 64 + i * 16 + (lane & 15)) * 80 + koff;
                ldsm4(base + off, ah[i]);
            }
            uint32_t bg[4][2], bu[4][2];
            #pragma unroll
            for (int j = 0; j < 2; j++) {
                const uint32_t off = (uint32_t)(wn * 32 + j * 16 + (lane & 15)) * 80 + koff;
                uint32_t t[4], u[4];
                ldsm4(base + 10240 + off, t);
                ldsm4(base + 20480 + off, u);
                bg[2*j][0] = t[0]; bg[2*j][1] = t[2];
                bg[2*j+1][0] = t[1]; bg[2*j+1][1] = t[3];
                bu[2*j][0] = u[0]; bu[2*j][1] = u[2];
                bu[2*j+1][0] = u[1]; bu[2*j+1][1] = u[3];
            }
            #pragma unroll
            for (int i = 0; i < 4; i++)
                #pragma unroll
                for (int n = 0; n < 4; n++) {
                    mma16816(accg[i][n], ah[i], bg[n]);
                    mma16816(accu[i][n], ah[i], bu[n]);
                }
        }
    }

    const long r0 = rowA + wm * 64 + (lane >> 2);
    const long c0 = rowB + wn * 32 + (lane & 3) * 2;
    #pragma unroll
    for (int i = 0; i < 4; i++) {
        #pragma unroll
        for (int n = 0; n < 4; n++) {
            #pragma unroll
            for (int h = 0; h < 2; h++) {
                const long row = r0 + i * 16 + h * 8;
                const long col = c0 + n * 8;
                const float v0 = gelu_f(accg[i][n][2*h + 0]) * accu[i][n][2*h + 0];
                const float v1 = gelu_f(accg[i][n][2*h + 1]) * accu[i][n][2*h + 1];
                *(uint32_t*)(Ch + row * (long)N + col) = pack2h(v0, v1);
            }
        }
    }
}

// ================= elementwise kernels =================
__global__ void rmsnorm_half_k(const float* __restrict__ x, const float* __restrict__ w,
                               __half* __restrict__ out) {
    const long row = blockIdx.x;
    const float* xr = x + row * (long)Dn;
    const int t4 = threadIdx.x * 4;
    float4 v = *(const float4*)(xr + t4);
    float ss = v.x*v.x + v.y*v.y + v.z*v.z + v.w*v.w;
    #pragma unroll
    for (int o = 16; o > 0; o >>= 1) ss += __shfl_xor_sync(0xffffffffu, ss, o);
    __shared__ float warps[8];
    if ((threadIdx.x & 31) == 0) warps[threadIdx.x >> 5] = ss;
    __syncthreads();
    float tot = 0.f;
    #pragma unroll
    for (int i = 0; i < 8; i++) tot += warps[i];
    const float inv = rsqrtf(tot * (1.0f / Dn) + 1.1920929e-07f);
    float4 wv = *(const float4*)(w + t4);
    uint2 hv;
    hv.x = pack2h(v.x*inv*wv.x, v.y*inv*wv.y);
    hv.y = pack2h(v.z*inv*wv.z, v.w*inv*wv.w);
    *(uint2*)(out + row * (long)Dn + t4) = hv;
}

__global__ void tohalf_k(const float* __restrict__ x, __half* __restrict__ out, long n4) {
    const long i = ((long)blockIdx.x * 256 + threadIdx.x);
    if (i >= n4) return;
    float4 v = *(const float4*)(x + i * 4);
    uint2 hv;
    hv.x = pack2h(v.x, v.y);
    hv.y = pack2h(v.z, v.w);
    *(uint2*)(out + i * 4) = hv;
}

__global__ void conv_kernel(const float* __restrict__ b1, const float* __restrict__ cbuf,
                            const float* __restrict__ cw, const float* __restrict__ cb,
                            float* __restrict__ out, __half* __restrict__ oh) {
    const long idx = (long)blockIdx.x * 256 + threadIdx.x;
    if (idx >= BTD) return;
    const int d = (int)(idx % Dn);
    const long td = idx / Dn;
    const int t = (int)(td % Tn);
    const int b = (int)(td / Tn);
    float acc = cb[d];
    #pragma unroll
    for (int k = 0; k < CONVK; k++) {
        const int tt = t + k - (CONVK - 1);
        float v = (tt >= 0) ? b1[((long)b * Tn + tt) * Dn + d]
                            : cbuf[((long)b * (CONVK - 1) + (t + k)) * Dn + d];
        acc = fmaf(v, cw[d * CONVK + k], acc);
    }
    out[idx] = acc;
    oh[idx] = __float2half_rn(acc);
}

// fused gate + scan with software-pipelined loads (prefetch t+4 chunk)
__global__ void scan_fused_k(const float* __restrict__ r, const float* __restrict__ ig,
                             const float* __restrict__ conv, const float* __restrict__ ll,
                             const float* __restrict__ h0, float* __restrict__ out,
                             float* __restrict__ newh) {
    const int idx = blockIdx.x * 256 + threadIdx.x;
    const int b = idx / Dn, d = idx % Dn;
    const float ls8 = -8.0f * log1pf(expf(-ll[d]));
    const long base = (long)b * Tn * Dn + d;
    float h = h0[idx];
    float cr[4], ci[4], cc[4];
    #pragma unroll
    for (int j = 0; j < 4; j++) {
        const long o = base + (long)j * Dn;
        cr[j] = r[o]; ci[j] = ig[o]; cc[j] = conv[o];
    }
    for (int t0 = 0; t0 < Tn; t0 += 4) {
        float nr[4], ni[4], nc[4];
        if (t0 + 4 < Tn) {
            #pragma unroll
            for (int j = 0; j < 4; j++) {
                const long o = base + (long)(t0 + 4 + j) * Dn;
                nr[j] = r[o]; ni[j] = ig[o]; nc[j] = conv[o];
            }
        }
        #pragma unroll
        for (int j = 0; j < 4; j++) {
            const float a = expf(cr[j] * ls8);
            const float gate = sqrtf(fmaxf((1.f - a) * (1.f + a), 1e-6f));
            h = fmaf(a, h, gate * ci[j] * cc[j]);
            out[base + (long)(t0 + j) * Dn] = h;
        }
        #pragma unroll
        for (int j = 0; j < 4; j++) { cr[j] = nr[j]; ci[j] = ni[j]; cc[j] = nc[j]; }
    }
    newh[idx] = h;
}

__global__ void cbuf_k(const float* __restrict__ b1, float* __restrict__ out) {
    const int idx = blockIdx.x * 256 + threadIdx.x;
    if (idx >= Bsz * (CONVK - 1) * Dn) return;
    const int d = idx % Dn;
    const int j = (idx / Dn) % (CONVK - 1);
    const int b = idx / (Dn * (CONVK - 1));
    out[idx] = b1[((long)b * Tn + (Tn - (CONVK - 1) + j)) * Dn + d];
}

// ================= host side =================
extern "C" void kernel_launch(void* const* d_in, const int* in_sizes, int n_in,
                              void* d_out, int out_size) {
    const float* x_seq   = (const float*)d_in[0];
    const float* h0      = (const float*)d_in[1];
    const float* convbuf = (const float*)d_in[2];
    const float* norm1_w = (const float*)d_in[3];
    const float* W1      = (const float*)d_in[4];
    const float* conv_w  = (const float*)d_in[5];
    const float* conv_b  = (const float*)d_in[6];
    const float* Wa      = (const float*)d_in[7];
    const float* ba      = (const float*)d_in[8];
    const float* Wx      = (const float*)d_in[9];
    const float* bx      = (const float*)d_in[10];
    const float* log_lam = (const float*)d_in[11];
    const float* W2      = (const float*)d_in[12];
    const float* Wout    = (const float*)d_in[13];
    const float* norm2_w = (const float*)d_in[14];
    const float* Wg      = (const float*)d_in[15];
    const float* Wu      = (const float*)d_in[16];
    const float* Wo      = (const float*)d_in[17];

    float* out_x2 = (float*)d_out;
    float* out_h  = out_x2 + (long)BTD;
    float* out_cb = out_h + (long)Bsz * Dn;

    float *p_b1, *p_conv, *p_r, *p_i, *p_scan, *p_x1;
    cudaGetSymbolAddress((void**)&p_b1, g_b1);
    cudaGetSymbolAddress((void**)&p_conv, g_conv);
    cudaGetSymbolAddress((void**)&p_r, g_r);
    cudaGetSymbolAddress((void**)&p_i, g_i);
    cudaGetSymbolAddress((void**)&p_scan, g_scan);
    cudaGetSymbolAddress((void**)&p_x1, g_x1);

    __half *nh, *ch, *ph, *n2h, *acth;
    cudaGetSymbolAddress((void**)&nh, g_norm_h);
    cudaGetSymbolAddress((void**)&ch, g_conv_h);
    cudaGetSymbolAddress((void**)&ph, g_prod_h);
    cudaGetSymbolAddress((void**)&n2h, g_n2_h);
    cudaGetSymbolAddress((void**)&acth, g_act_h);

    __half *w1h, *wah, *wxh, *w2h, *woh, *wgh, *wuh, *wo2h;
    cudaGetSymbolAddress((void**)&w1h, g_w1_h);
    cudaGetSymbolAddress((void**)&wah, g_wa_h);
    cudaGetSymbolAddress((void**)&wxh, g_wx_h);
    cudaGetSymbolAddress((void**)&w2h, g_w2_h);
    cudaGetSymbolAddress((void**)&woh, g_wo_h);
    cudaGetSymbolAddress((void**)&wgh, g_wg_h);
    cudaGetSymbolAddress((void**)&wuh, g_wu_h);
    cudaGetSymbolAddress((void**)&wo2h, g_wout2_h);

    cudaFuncSetAttribute(gemm_mma<0,0>, cudaFuncAttributeMaxDynamicSharedMemorySize, S_SMEM);
    cudaFuncSetAttribute(gemm_mma<1,0>, cudaFuncAttributeMaxDynamicSharedMemorySize, S_SMEM);
    cudaFuncSetAttribute(gemm_mma<3,0>, cudaFuncAttributeMaxDynamicSharedMemorySize, S_SMEM);
    cudaFuncSetAttribute(gemm_mma<5,1>, cudaFuncAttributeMaxDynamicSharedMemorySize, S_SMEM);
    cudaFuncSetAttribute(gemm_dual,     cudaFuncAttributeMaxDynamicSharedMemorySize, D_SMEM);

    const dim3 gD(Dn / 128, BT / 256);    // (8, 64)
    const dim3 gH(Hn / 128, BT / 128);    // (32, 128)  dual
    const int EW = (BTD + 255) / 256;

    // weight fp16 conversion
    tohalf_k<<<(Dn*Dn/4 + 255)/256, 256>>>(W1,   w1h, Dn*Dn/4);
    tohalf_k<<<(Dn*Dn/4 + 255)/256, 256>>>(Wa,   wah, Dn*Dn/4);
    tohalf_k<<<(Dn*Dn/4 + 255)/256, 256>>>(Wx,   wxh, Dn*Dn/4);
    tohalf_k<<<(Dn*Dn/4 + 255)/256, 256>>>(W2,   w2h, Dn*Dn/4);
    tohalf_k<<<(Dn*Dn/4 + 255)/256, 256>>>(Wout, woh, Dn*Dn/4);
    tohalf_k<<<((long)Hn*Dn/4 + 255)/256, 256>>>(Wg, wgh, (long)Hn*Dn/4);
    tohalf_k<<<((long)Hn*Dn/4 + 255)/256, 256>>>(Wu, wuh, (long)Hn*Dn/4);
    tohalf_k<<<((long)Dn*Hn/4 + 255)/256, 256>>>(Wo, wo2h, (long)Dn*Hn/4);

    // 1. rmsnorm1 -> fp16
    rmsnorm_half_k<<<BT, 256>>>(x_seq, norm1_w, nh);
    // 2. b1 = normed @ W1^T
    gemm_mma<0,0><<<gD, 256, S_SMEM>>>(nh, w1h, p_b1, nullptr, nullptr, nullptr, Dn, Dn);
    // 3. conv (+fp16) and new_conv_buf
    conv_kernel<<<EW, 256>>>(p_b1, convbuf, conv_w, conv_b, p_conv, ch);
    cbuf_k<<<(Bsz * (CONVK - 1) * Dn + 255) / 256, 256>>>(p_b1, out_cb);
    // 4/5. r, i = sigmoid(conv @ {Wa,Wx}^T + {ba,bx})
    gemm_mma<1,0><<<gD, 256, S_SMEM>>>(ch, wah, p_r, nullptr, nullptr, ba, Dn, Dn);
    gemm_mma<1,0><<<gD, 256, S_SMEM>>>(ch, wxh, p_i, nullptr, nullptr, bx, Dn, Dn);
    // 6. fused gate + scan
    scan_fused_k<<<(Bsz * Dn) / 256, 256>>>(p_r, p_i, p_conv, log_lam, h0, p_scan, out_h);
    // 7. prod = gelu(normed @ W2^T) * scan -> fp16  (fused epilogue)
    gemm_mma<5,1><<<gD, 256, S_SMEM>>>(nh, w2h, nullptr, ph, p_scan, nullptr, Dn, Dn);
    // 8. x1 = x_seq + prod @ Wout^T
    gemm_mma<3,0><<<gD, 256, S_SMEM>>>(ph, woh, p_x1, nullptr, x_seq, nullptr, Dn, Dn);
    // 9. n2 = rmsnorm(x1) -> fp16
    rmsnorm_half_k<<<BT, 256>>>(p_x1, norm2_w, n2h);
    // 10. act = gelu(n2@Wg^T) * (n2@Wu^T) -> fp16  (dual GEMM)
    gemm_dual<<<gH, 256, D_SMEM>>>(n2h, wgh, wuh, acth, Hn, Dn);
    // 11. x2 = x1 + act @ Wo^T
    gemm_mma<3,0><<<gD, 256, S_SMEM>>>(acth, wo2h, out_x2, nullptr, p_x1, nullptr, Dn, Hn);
}